// round 4
// baseline (speedup 1.0000x reference)
#include <cuda_runtime.h>

#define NCAP (1 << 20)          // capacity (reference uses exactly 2^20 points)
#define NBINS 32768             // 15-bit Morton spatial bucket (32^3 grid)
#define HASH_MASK 0x7FFFFu
#define P2 2654435761u
#define P3 805459861u

// ---------------- scratch (allocation-free: __device__ globals) ----------------
__device__ unsigned int g_hist[NBINS];
__device__ unsigned int g_offsets[NBINS];
__device__ float4       g_sortedXyz[NCAP];   // xyz + original index in .w

static __device__ __constant__ float c_resf[16] = {
    16.f, 20.f, 25.f, 32.f, 40.f, 50.f, 64.f, 80.f,
    101.f, 128.f, 161.f, 203.f, 256.f, 322.f, 406.f, 512.f
};

__device__ __forceinline__ unsigned part1by2(unsigned v) {
    v &= 0x3FFu;
    v = (v | (v << 16)) & 0x030000FFu;
    v = (v | (v << 8))  & 0x0300F00Fu;
    v = (v | (v << 4))  & 0x030C30C3u;
    v = (v | (v << 2))  & 0x09249249u;
    return v;
}

__device__ __forceinline__ unsigned bucket_key(float x, float y, float z) {
    unsigned cx = min((unsigned)(x * 32.0f), 31u);
    unsigned cy = min((unsigned)(y * 32.0f), 31u);
    unsigned cz = min((unsigned)(z * 32.0f), 31u);
    return (part1by2(cx) << 2) | (part1by2(cy) << 1) | part1by2(cz);
}

// ---------------- pass 0: zero histogram ----------------
__global__ void zero_hist_kernel() {
    int i = blockIdx.x * blockDim.x + threadIdx.x;
    if (i < NBINS / 4) ((uint4*)g_hist)[i] = make_uint4(0u, 0u, 0u, 0u);
}

// ---------------- pass 1: histogram (fire-and-forget REDG) ----------------
__global__ void hist_kernel(const float* __restrict__ xyz, int n_pts) {
    int i = blockIdx.x * blockDim.x + threadIdx.x;
    if (i >= n_pts) return;
    float x = xyz[3 * i + 0], y = xyz[3 * i + 1], z = xyz[3 * i + 2];
    atomicAdd(&g_hist[bucket_key(x, y, z)], 1u);
}

// ---------------- pass 2: exclusive scan of 32768 bins (single block) ----------------
__global__ void scan_kernel() {
    __shared__ unsigned partial[1024];
    int t = threadIdx.x;                 // 1024 threads, 32 bins each
    unsigned s = 0;
    int base = t * 32;
    #pragma unroll
    for (int k = 0; k < 32; k++) s += g_hist[base + k];
    partial[t] = s;
    __syncthreads();
    for (int d = 1; d < 1024; d <<= 1) {
        unsigned v = (t >= d) ? partial[t - d] : 0u;
        __syncthreads();
        partial[t] += v;
        __syncthreads();
    }
    unsigned run = (t == 0) ? 0u : partial[t - 1];
    #pragma unroll
    for (int k = 0; k < 32; k++) {
        unsigned c = g_hist[base + k];
        g_offsets[base + k] = run;
        run += c;
    }
}

// ---------------- pass 3: scatter (2 independent points/thread for ILP) ----------------
__global__ void scatter_kernel(const float* __restrict__ xyz, int n_pts) {
    int i0 = (blockIdx.x * blockDim.x + threadIdx.x) * 2;
    int i1 = i0 + 1;

    float x0, y0, z0, x1 = 0.f, y1 = 0.f, z1 = 0.f;
    bool v0 = (i0 < n_pts), v1 = (i1 < n_pts);
    if (v0) { x0 = xyz[3 * i0 + 0]; y0 = xyz[3 * i0 + 1]; z0 = xyz[3 * i0 + 2]; }
    if (v1) { x1 = xyz[3 * i1 + 0]; y1 = xyz[3 * i1 + 1]; z1 = xyz[3 * i1 + 2]; }

    unsigned p0 = 0, p1 = 0;
    if (v0) p0 = atomicAdd(&g_offsets[bucket_key(x0, y0, z0)], 1u);
    if (v1) p1 = atomicAdd(&g_offsets[bucket_key(x1, y1, z1)], 1u);
    if (v0) g_sortedXyz[p0] = make_float4(x0, y0, z0, __int_as_float(i0));
    if (v1) g_sortedXyz[p1] = make_float4(x1, y1, z1, __int_as_float(i1));
}

// ---------------- main: level-major hash-grid encode over sorted points ----------------
// block = 512 threads = 16 warps; warp w handles level w for 32 consecutive sorted points.
__global__ void __launch_bounds__(512, 4) hashgrid_sorted_kernel(
    const float2* __restrict__ tables,
    float2* __restrict__ out, int n_pts)
{
    __shared__ float2 out_s[32][18];     // 144B rows: 16B-aligned, modest conflicts
    __shared__ int    orig_s[32];

    const int lane  = threadIdx.x & 31;
    const int level = threadIdx.x >> 5;  // 0..15
    const int pos   = blockIdx.x * 32 + lane;

    bool valid = (pos < n_pts);
    float2 result = make_float2(0.f, 0.f);
    int orig = -1;

    if (valid) {
        float4 v = g_sortedXyz[pos];
        float x = v.x, y = v.y, z = v.z;
        orig = __float_as_int(v.w);

        float resf = c_resf[level];
        float cell = __fdiv_rn(1.0f, resf);

        // exact match to jnp.floor(x / cell)
        float fx = floorf(__fdiv_rn(x, cell));
        float fy = floorf(__fdiv_rn(y, cell));
        float fz = floorf(__fdiv_rn(z, cell));
        int ix = (int)fx, iy = (int)fy, iz = (int)fz;

        float minx = fx * cell, miny = fy * cell, minz = fz * cell;
        float dx = __fdividef(x - minx, (minx + cell) - minx);
        float dy = __fdividef(y - miny, (miny + cell) - miny);
        float dz = __fdividef(z - minz, (minz + cell) - minz);

        unsigned hx0 = (unsigned)ix,        hx1 = hx0 + 1u;
        unsigned hy0 = (unsigned)iy * P2,   hy1 = hy0 + P2;
        unsigned hz0 = (unsigned)iz * P3,   hz1 = hz0 + P3;

        const float2* __restrict__ table = tables + ((size_t)level << 19);

#define HHH(a, b, c) (((a) ^ (b) ^ (c)) & HASH_MASK)
        float2 e0 = __ldg(table + HHH(hx0, hy0, hz0));
        float2 e1 = __ldg(table + HHH(hx0, hy0, hz1));
        float2 e2 = __ldg(table + HHH(hx0, hy1, hz0));
        float2 e3 = __ldg(table + HHH(hx0, hy1, hz1));
        float2 e4 = __ldg(table + HHH(hx1, hy0, hz0));
        float2 e5 = __ldg(table + HHH(hx1, hy0, hz1));
        float2 e6 = __ldg(table + HHH(hx1, hy1, hz0));
        float2 e7 = __ldg(table + HHH(hx1, hy1, hz1));
#undef HHH

        float c00x = fmaf(dx, e4.x - e0.x, e0.x);
        float c00y = fmaf(dx, e4.y - e0.y, e0.y);
        float c01x = fmaf(dx, e5.x - e1.x, e1.x);
        float c01y = fmaf(dx, e5.y - e1.y, e1.y);
        float c10x = fmaf(dx, e6.x - e2.x, e2.x);
        float c10y = fmaf(dx, e6.y - e2.y, e2.y);
        float c11x = fmaf(dx, e7.x - e3.x, e3.x);
        float c11y = fmaf(dx, e7.y - e3.y, e3.y);

        float c0x = fmaf(dy, c10x - c00x, c00x);
        float c0y = fmaf(dy, c10y - c00y, c00y);
        float c1x = fmaf(dy, c11x - c01x, c01x);
        float c1y = fmaf(dy, c11y - c01y, c01y);

        result = make_float2(fmaf(dz, c1x - c0x, c0x),
                             fmaf(dz, c1y - c0y, c0y));
    }

    out_s[lane][level] = result;
    if (level == 0) orig_s[lane] = orig;
    __syncthreads();

    // cooperative scatter: 8 threads x float4 = one 128B line per point
    if (threadIdx.x < 256) {
        int pl = threadIdx.x >> 3;       // local point 0..31
        int c4 = threadIdx.x & 7;        // float4 chunk 0..7
        int o  = orig_s[pl];
        if (o >= 0) {
            float4 v = *(const float4*)&out_s[pl][c4 * 2];
            ((float4*)out)[(size_t)o * 8 + c4] = v;
        }
    }
}

extern "C" void kernel_launch(void* const* d_in, const int* in_sizes, int n_in,
                              void* d_out, int out_size)
{
    const float* xyz;
    const float2* tables;
    int n_xyz_elems;
    if (in_sizes[0] < in_sizes[1]) {
        xyz = (const float*)d_in[0];
        tables = (const float2*)d_in[1];
        n_xyz_elems = in_sizes[0];
    } else {
        xyz = (const float*)d_in[1];
        tables = (const float2*)d_in[0];
        n_xyz_elems = in_sizes[1];
    }
    int n_pts = n_xyz_elems / 3;

    zero_hist_kernel<<<(NBINS / 4 + 255) / 256, 256>>>();
    hist_kernel<<<(n_pts + 255) / 256, 256>>>(xyz, n_pts);
    scan_kernel<<<1, 1024>>>();
    int half = (n_pts + 1) / 2;
    scatter_kernel<<<(half + 255) / 256, 256>>>(xyz, n_pts);

    int n_chunks = (n_pts + 31) / 32;
    hashgrid_sorted_kernel<<<n_chunks, 512>>>(tables, (float2*)d_out, n_pts);
}

// round 5
// speedup vs baseline: 1.0248x; 1.0248x over previous
#include <cuda_runtime.h>

#define NCAP (1 << 20)          // capacity (reference uses exactly 2^20 points)
#define NBINS 32768             // 15-bit spatial bucket (32^3 grid)
#define HASH_MASK 0x7FFFFu
#define P2 2654435761u
#define P3 805459861u

// ---------------- scratch (allocation-free: __device__ globals) ----------------
__device__ unsigned int g_hist[NBINS];
__device__ unsigned int g_offsets[NBINS];
__device__ float4       g_sortedXyz[NCAP];   // xyz + original index in .w

static __device__ __constant__ float c_resf[16] = {
    16.f, 20.f, 25.f, 32.f, 40.f, 50.f, 64.f, 80.f,
    101.f, 128.f, 161.f, 203.f, 256.f, 322.f, 406.f, 512.f
};

__device__ __forceinline__ unsigned bucket_key(float x, float y, float z) {
    unsigned cx = min((unsigned)(x * 32.0f), 31u);
    unsigned cy = min((unsigned)(y * 32.0f), 31u);
    unsigned cz = min((unsigned)(z * 32.0f), 31u);
    return (cx << 10) | (cy << 5) | cz;
}

// ---------------- pass 0: zero histogram ----------------
__global__ void zero_hist_kernel() {
    int i = blockIdx.x * blockDim.x + threadIdx.x;
    if (i < NBINS / 4) ((uint4*)g_hist)[i] = make_uint4(0u, 0u, 0u, 0u);
}

// ---------------- pass 1: histogram ----------------
__global__ void hist_kernel(const float* __restrict__ xyz, int n_pts) {
    int i = blockIdx.x * blockDim.x + threadIdx.x;
    if (i >= n_pts) return;
    float x = xyz[3 * i + 0], y = xyz[3 * i + 1], z = xyz[3 * i + 2];
    atomicAdd(&g_hist[bucket_key(x, y, z)], 1u);
}

// ---------------- pass 2: exclusive scan of 32768 bins (single block) ----------------
__global__ void scan_kernel() {
    __shared__ unsigned partial[1024];
    int t = threadIdx.x;                 // 1024 threads, 32 bins each
    unsigned s = 0;
    int base = t * 32;
    #pragma unroll
    for (int k = 0; k < 32; k++) s += g_hist[base + k];
    partial[t] = s;
    __syncthreads();
    for (int d = 1; d < 1024; d <<= 1) {
        unsigned v = (t >= d) ? partial[t - d] : 0u;
        __syncthreads();
        partial[t] += v;
        __syncthreads();
    }
    unsigned run = (t == 0) ? 0u : partial[t - 1];
    #pragma unroll
    for (int k = 0; k < 32; k++) {
        unsigned c = g_hist[base + k];
        g_offsets[base + k] = run;
        run += c;
    }
}

// ---------------- pass 3: scatter points into bucket order ----------------
__global__ void scatter_kernel(const float* __restrict__ xyz, int n_pts) {
    int i = blockIdx.x * blockDim.x + threadIdx.x;
    if (i >= n_pts) return;
    float x = xyz[3 * i + 0], y = xyz[3 * i + 1], z = xyz[3 * i + 2];
    unsigned key = bucket_key(x, y, z);
    unsigned p = atomicAdd(&g_offsets[key], 1u);
    g_sortedXyz[p] = make_float4(x, y, z, __int_as_float(i));
}

// ---------------- main: level-major hash-grid encode over sorted points ----------------
// block = 512 threads = 16 warps; warp w handles level w for 32 consecutive sorted points.
// x-pair trick: PRIMES[0]==1, so for even ix the two x-corners of each (y,z)
// combo sit at table indices h and h^1 -> one 16B-aligned float4 load.
__global__ void __launch_bounds__(512, 4) hashgrid_sorted_kernel(
    const float2* __restrict__ tables,
    float2* __restrict__ out, int n_pts)
{
    __shared__ float2 out_s[32][17];     // padded to dodge bank conflicts
    __shared__ int    orig_s[32];

    const int lane  = threadIdx.x & 31;
    const int level = threadIdx.x >> 5;  // 0..15
    const int pos   = blockIdx.x * 32 + lane;

    bool valid = (pos < n_pts);
    float2 result = make_float2(0.f, 0.f);
    int orig = -1;

    if (valid) {
        float4 v = g_sortedXyz[pos];
        float x = v.x, y = v.y, z = v.z;
        orig = __float_as_int(v.w);

        float resf = c_resf[level];
        float cell = __fdiv_rn(1.0f, resf);

        // exact match to jnp.floor(x / cell)
        float fx = floorf(__fdiv_rn(x, cell));
        float fy = floorf(__fdiv_rn(y, cell));
        float fz = floorf(__fdiv_rn(z, cell));
        int ix = (int)fx, iy = (int)fy, iz = (int)fz;

        float minx = fx * cell, miny = fy * cell, minz = fz * cell;
        float dx = __fdividef(x - minx, (minx + cell) - minx);
        float dy = __fdividef(y - miny, (miny + cell) - miny);
        float dz = __fdividef(z - minz, (minz + cell) - minz);

        unsigned hx0 = (unsigned)ix,        hx1 = hx0 + 1u;
        unsigned hy0 = (unsigned)iy * P2,   hy1 = hy0 + P2;
        unsigned hz0 = (unsigned)iz * P3,   hz1 = hz0 + P3;

        const float2* __restrict__ table = tables + ((size_t)level << 19);

        // hashes for the x0 corners of the 4 (y,z) combos
        unsigned h00 = (hx0 ^ hy0 ^ hz0) & HASH_MASK;  // (x0,y0,z0) -> e0 / e4
        unsigned h01 = (hx0 ^ hy0 ^ hz1) & HASH_MASK;  // (x0,y0,z1) -> e1 / e5
        unsigned h10 = (hx0 ^ hy1 ^ hz0) & HASH_MASK;  // (x0,y1,z0) -> e2 / e6
        unsigned h11 = (hx0 ^ hy1 ^ hz1) & HASH_MASK;  // (x0,y1,z1) -> e3 / e7

        float2 e0, e1, e2, e3, e4, e5, e6, e7;

        if (!(hx0 & 1u)) {
            // ix even: x1-corner hash = h ^ 1 -> adjacent entries, one float4 each
            const float4* __restrict__ table4 = (const float4*)table;
            float4 v00 = __ldg(table4 + (h00 >> 1));
            float4 v01 = __ldg(table4 + (h01 >> 1));
            float4 v10 = __ldg(table4 + (h10 >> 1));
            float4 v11 = __ldg(table4 + (h11 >> 1));
            // if h is even, x0-corner at low half; else at high half
            if (h00 & 1u) { e4 = make_float2(v00.x, v00.y); e0 = make_float2(v00.z, v00.w); }
            else          { e0 = make_float2(v00.x, v00.y); e4 = make_float2(v00.z, v00.w); }
            if (h01 & 1u) { e5 = make_float2(v01.x, v01.y); e1 = make_float2(v01.z, v01.w); }
            else          { e1 = make_float2(v01.x, v01.y); e5 = make_float2(v01.z, v01.w); }
            if (h10 & 1u) { e6 = make_float2(v10.x, v10.y); e2 = make_float2(v10.z, v10.w); }
            else          { e2 = make_float2(v10.x, v10.y); e6 = make_float2(v10.z, v10.w); }
            if (h11 & 1u) { e7 = make_float2(v11.x, v11.y); e3 = make_float2(v11.z, v11.w); }
            else          { e3 = make_float2(v11.x, v11.y); e7 = make_float2(v11.z, v11.w); }
        } else {
            unsigned g00 = (hx1 ^ hy0 ^ hz0) & HASH_MASK;
            unsigned g01 = (hx1 ^ hy0 ^ hz1) & HASH_MASK;
            unsigned g10 = (hx1 ^ hy1 ^ hz0) & HASH_MASK;
            unsigned g11 = (hx1 ^ hy1 ^ hz1) & HASH_MASK;
            e0 = __ldg(table + h00);
            e1 = __ldg(table + h01);
            e2 = __ldg(table + h10);
            e3 = __ldg(table + h11);
            e4 = __ldg(table + g00);
            e5 = __ldg(table + g01);
            e6 = __ldg(table + g10);
            e7 = __ldg(table + g11);
        }

        float c00x = fmaf(dx, e4.x - e0.x, e0.x);
        float c00y = fmaf(dx, e4.y - e0.y, e0.y);
        float c01x = fmaf(dx, e5.x - e1.x, e1.x);
        float c01y = fmaf(dx, e5.y - e1.y, e1.y);
        float c10x = fmaf(dx, e6.x - e2.x, e2.x);
        float c10y = fmaf(dx, e6.y - e2.y, e2.y);
        float c11x = fmaf(dx, e7.x - e3.x, e3.x);
        float c11y = fmaf(dx, e7.y - e3.y, e3.y);

        float c0x = fmaf(dy, c10x - c00x, c00x);
        float c0y = fmaf(dy, c10y - c00y, c00y);
        float c1x = fmaf(dy, c11x - c01x, c01x);
        float c1y = fmaf(dy, c11y - c01y, c01y);

        result = make_float2(fmaf(dz, c1x - c0x, c0x),
                             fmaf(dz, c1y - c0y, c0y));
    }

    out_s[lane][level] = result;
    if (level == 0) orig_s[lane] = orig;
    __syncthreads();

    // cooperative scatter: one full 128B line per point
    int pl = threadIdx.x >> 4;           // local point 0..31
    int c  = threadIdx.x & 15;           // level/feature pair 0..15
    int o  = orig_s[pl];
    if (o >= 0) out[(size_t)o * 16 + c] = out_s[pl][c];
}

extern "C" void kernel_launch(void* const* d_in, const int* in_sizes, int n_in,
                              void* d_out, int out_size)
{
    const float* xyz;
    const float2* tables;
    int n_xyz_elems;
    if (in_sizes[0] < in_sizes[1]) {
        xyz = (const float*)d_in[0];
        tables = (const float2*)d_in[1];
        n_xyz_elems = in_sizes[0];
    } else {
        xyz = (const float*)d_in[1];
        tables = (const float2*)d_in[0];
        n_xyz_elems = in_sizes[1];
    }
    int n_pts = n_xyz_elems / 3;

    zero_hist_kernel<<<(NBINS / 4 + 255) / 256, 256>>>();
    hist_kernel<<<(n_pts + 255) / 256, 256>>>(xyz, n_pts);
    scan_kernel<<<1, 1024>>>();
    scatter_kernel<<<(n_pts + 255) / 256, 256>>>(xyz, n_pts);

    int n_chunks = (n_pts + 31) / 32;
    hashgrid_sorted_kernel<<<n_chunks, 512>>>(tables, (float2*)d_out, n_pts);
}